// round 4
// baseline (speedup 1.0000x reference)
#include <cuda_runtime.h>

#define BB 2048
#define TT 512
#define II 64
#define G  9      // 3 gates * H=3
#define SLOT 12   // padded floats per (t,b): 3 hidden-idx groups x float4 (r,z,n,pad)

// Scratch: xW0 precomputed, layout [T][B][SLOT]. Group g holds (xr_g, xz_g, xn_g, 0)
// so the recurrence lane for hidden-index g does ONE LDG.128 per step.
__device__ float g_xw0[(size_t)TT * BB * SLOT];

__device__ __forceinline__ float sigm(float x) {
    return __fdividef(1.0f, 1.0f + __expf(-x));
}

__device__ __forceinline__ float tanh_fast(float x) {
    float xc = fmaxf(x, -20.0f);
    float e = __expf(-2.0f * xc);
    return __fdividef(1.0f - e, 1.0f + e);
}

// -------------------------------------------------------------------------
// Phase A: xw0 = x @ W_ih0^T + b_ih0, written as [t][b][g*4 + {r,z,n,pad}]
// -------------------------------------------------------------------------
__global__ void __launch_bounds__(256) phaseA(
    const float* __restrict__ x,
    const float* __restrict__ W_ih0,
    const float* __restrict__ b_ih0)
{
    __shared__ float Ws[G * II];
    __shared__ float bs[G];
    for (int i = threadIdx.x; i < G * II; i += blockDim.x) Ws[i] = W_ih0[i];
    if (threadIdx.x < G) bs[threadIdx.x] = b_ih0[threadIdx.x];
    __syncthreads();

    int idx = blockIdx.x * blockDim.x + threadIdx.x;   // 0 .. B*T-1
    int b = idx & (BB - 1);
    int t = idx >> 11;

    const float4* xp = reinterpret_cast<const float4*>(x + ((size_t)b * TT + t) * II);
    const float4* wp = reinterpret_cast<const float4*>(Ws);

    float acc[G];
#pragma unroll
    for (int g = 0; g < G; g++) acc[g] = bs[g];

#pragma unroll
    for (int i = 0; i < II / 4; i++) {
        float4 xv = xp[i];
#pragma unroll
        for (int g = 0; g < G; g++) {
            float4 wv = wp[g * (II / 4) + i];
            acc[g] += xv.x * wv.x + xv.y * wv.y + xv.z * wv.z + xv.w * wv.w;
        }
    }

    float4* o = reinterpret_cast<float4*>(g_xw0 + ((size_t)t * BB + b) * SLOT);
    o[0] = make_float4(acc[0], acc[3], acc[6], 0.f);   // hidden idx 0: r,z,n
    o[1] = make_float4(acc[1], acc[4], acc[7], 0.f);   // hidden idx 1
    o[2] = make_float4(acc[2], acc[5], acc[8], 0.f);   // hidden idx 2
}

// -------------------------------------------------------------------------
// Phase B: 8 lanes per batch element.
//   j = tid & 7:  j in {0,1,2}  -> layer 0, hidden index g = j
//                 j in {3,4,5}  -> layer 1 (one step behind), g = j-3
//                 j in {6,7}    -> idle compute (never stored)
// h state lives one component per lane; exchanged via shfl each step.
// -------------------------------------------------------------------------
__global__ void __launch_bounds__(128, 1) gru_rec(
    const float* __restrict__ W_hh0, const float* __restrict__ b_hh0,
    const float* __restrict__ W_ih1, const float* __restrict__ b_ih1,
    const float* __restrict__ W_hh1, const float* __restrict__ b_hh1,
    float* __restrict__ out)
{
    const int tid  = blockIdx.x * blockDim.x + threadIdx.x;
    const int lane = threadIdx.x & 31;
    const int j    = tid & 7;
    const int e    = tid >> 3;          // batch element
    const int g    = j % 3;             // hidden index handled by this lane
    const bool l1  = (j >= 3);
    const int base = lane & ~7;         // lane of this element's group start

    // Per-lane recurrent weights: rows {g, 3+g, 6+g} of own layer's W_hh.
    const float* whh_src = l1 ? W_hh1 : W_hh0;
    const float* bhh_src = l1 ? b_hh1 : b_hh0;
    float whh[3][3], bh[3], wih[3][3], bi[3];
#pragma unroll
    for (int q = 0; q < 3; q++) {       // q: gate type (r=0, z=1, n=2)
        int row = q * 3 + g;
        bh[q] = __ldg(bhh_src + row);
        bi[q] = __ldg(b_ih1 + row);
#pragma unroll
        for (int k = 0; k < 3; k++) {
            whh[q][k] = __ldg(whh_src + row * 3 + k);
            wih[q][k] = __ldg(W_ih1 + row * 3 + k);
        }
    }

    float h = 0.f;                      // this lane's h-component (own layer)

    const int XSTR = BB * 3;            // per-timestep stride in float4 units
    const float4* xp = reinterpret_cast<const float4*>(g_xw0) + (size_t)e * 3 + g;

    // 3-deep prefetch (covers ~260cyc L2 latency); only layer-0 lanes load.
    float4 p0 = make_float4(0,0,0,0), p1 = p0, p2 = p0;
    if (j < 3) {
        p0 = xp[0];
        p1 = xp[XSTR];
        p2 = xp[2 * (size_t)XSTR];
    }

#pragma unroll 2
    for (int t = 0; t < TT; t++) {
        // Exchange state. a* = h0^{t-1}; b* = h1^{t-2}.
        float a0 = __shfl_sync(0xffffffffu, h, base + 0);
        float a1 = __shfl_sync(0xffffffffu, h, base + 1);
        float a2 = __shfl_sync(0xffffffffu, h, base + 2);
        float c0 = __shfl_sync(0xffffffffu, h, base + 3);
        float c1 = __shfl_sync(0xffffffffu, h, base + 4);
        float c2 = __shfl_sync(0xffffffffu, h, base + 5);
        float o0 = l1 ? c0 : a0;        // own-layer previous h
        float o1 = l1 ? c1 : a1;
        float o2 = l1 ? c2 : a2;

        // Recurrent gate pre-activations for this lane's hidden index.
        float ghr = fmaf(whh[0][2], o2, fmaf(whh[0][1], o1, fmaf(whh[0][0], o0, bh[0])));
        float ghz = fmaf(whh[1][2], o2, fmaf(whh[1][1], o1, fmaf(whh[1][0], o0, bh[1])));
        float ghn = fmaf(whh[2][2], o2, fmaf(whh[2][1], o1, fmaf(whh[2][0], o0, bh[2])));

        // Input-side pre-activations: layer0 from scratch, layer1 from h0^{t-1}.
        float xr1 = fmaf(wih[0][2], a2, fmaf(wih[0][1], a1, fmaf(wih[0][0], a0, bi[0])));
        float xz1 = fmaf(wih[1][2], a2, fmaf(wih[1][1], a1, fmaf(wih[1][0], a0, bi[1])));
        float xn1 = fmaf(wih[2][2], a2, fmaf(wih[2][1], a1, fmaf(wih[2][0], a0, bi[2])));
        float xr = l1 ? xr1 : p0.x;
        float xz = l1 ? xz1 : p0.y;
        float xn = l1 ? xn1 : p0.z;

        // Rotate prefetch pipeline; fetch t+3.
        p0 = p1; p1 = p2;
        if (j < 3 && t + 3 < TT)
            p2 = xp[(size_t)(t + 3) * XSTR];

        float r  = sigm(xr + ghr);
        float z  = sigm(xz + ghz);
        float n  = tanh_fast(fmaf(r, ghn, xn));
        float hn = fmaf(z, h - n, n);

        // Layer-1 lanes skip their (invalid) step at t==0.
        bool commit = (!l1) || (t > 0);
        h = commit ? hn : h;
    }

    // Epilogue: final layer-1 step (consumes h0^{T-1}).
    {
        float a0 = __shfl_sync(0xffffffffu, h, base + 0);
        float a1 = __shfl_sync(0xffffffffu, h, base + 1);
        float a2 = __shfl_sync(0xffffffffu, h, base + 2);
        float c0 = __shfl_sync(0xffffffffu, h, base + 3);
        float c1 = __shfl_sync(0xffffffffu, h, base + 4);
        float c2 = __shfl_sync(0xffffffffu, h, base + 5);

        float ghr = fmaf(whh[0][2], c2, fmaf(whh[0][1], c1, fmaf(whh[0][0], c0, bh[0])));
        float ghz = fmaf(whh[1][2], c2, fmaf(whh[1][1], c1, fmaf(whh[1][0], c0, bh[1])));
        float ghn = fmaf(whh[2][2], c2, fmaf(whh[2][1], c1, fmaf(whh[2][0], c0, bh[2])));
        float xr  = fmaf(wih[0][2], a2, fmaf(wih[0][1], a1, fmaf(wih[0][0], a0, bi[0])));
        float xz  = fmaf(wih[1][2], a2, fmaf(wih[1][1], a1, fmaf(wih[1][0], a0, bi[1])));
        float xn  = fmaf(wih[2][2], a2, fmaf(wih[2][1], a1, fmaf(wih[2][0], a0, bi[2])));

        float r  = sigm(xr + ghr);
        float z  = sigm(xz + ghz);
        float n  = tanh_fast(fmaf(r, ghn, xn));
        float hn = fmaf(z, h - n, n);
        if (l1) h = hn;
    }

    if (j >= 3 && j < 6)
        out[e * 3 + (j - 3)] = h;
}

extern "C" void kernel_launch(void* const* d_in, const int* in_sizes, int n_in,
                              void* d_out, int out_size)
{
    const float* x     = (const float*)d_in[0];
    const float* W_ih0 = (const float*)d_in[1];
    const float* W_hh0 = (const float*)d_in[2];
    const float* b_ih0 = (const float*)d_in[3];
    const float* b_hh0 = (const float*)d_in[4];
    const float* W_ih1 = (const float*)d_in[5];
    const float* W_hh1 = (const float*)d_in[6];
    const float* b_ih1 = (const float*)d_in[7];
    const float* b_hh1 = (const float*)d_in[8];
    float* out = (float*)d_out;

    phaseA<<<(BB * TT) / 256, 256>>>(x, W_ih0, b_ih0);
    gru_rec<<<(BB * 8) / 128, 128>>>(W_hh0, b_hh0, W_ih1, b_ih1, W_hh1, b_hh1, out);
}

// round 5
// speedup vs baseline: 1.5568x; 1.5568x over previous
#include <cuda_runtime.h>

#define BB 2048
#define TT 512
#define II 64

// Scratch, layout [t][gf][b] as float4: slot (t*3+gf)*BB + b holds
// (xr_gf, xz_gf, xn_gf, 0) for hidden index gf of element b at time t.
// Padded by 8 timesteps so the in-loop prefetch never needs a bounds check.
__device__ float4 g_xw4[(size_t)(TT + 8) * 3 * BB];

__device__ __forceinline__ float sigm(float x) {
    return __fdividef(1.0f, 1.0f + __expf(-x));
}
__device__ __forceinline__ float tanh_fast(float x) {
    float xc = fmaxf(x, -20.0f);
    float e = __expf(-2.0f * xc);
    return __fdividef(1.0f - e, 1.0f + e);
}

// ---------------------------------------------------------------------------
// Phase A: 4 lanes per (b,t) cell. Lane strip = interleaved 16B chunks so each
// LDG.128 is stride-16B across the quad -> ~4 wavefronts per instruction.
// Butterfly reduce over the quad; lanes sub=0..2 store the 3 output float4s.
// ---------------------------------------------------------------------------
__global__ void __launch_bounds__(256) phaseA(
    const float* __restrict__ x,
    const float* __restrict__ W_ih0,
    const float* __restrict__ b_ih0)
{
    __shared__ float4 Ws4[9 * 16];   // W_ih0 as 144 float4
    __shared__ float bs[9];
    if (threadIdx.x < 144) Ws4[threadIdx.x] = ((const float4*)W_ih0)[threadIdx.x];
    if (threadIdx.x < 9)   bs[threadIdx.x] = b_ih0[threadIdx.x];
    __syncthreads();

    int gw   = blockIdx.x * 8 + (threadIdx.x >> 5);  // global warp: 8 cells (same b, consecutive t)
    int lane = threadIdx.x & 31;
    int b    = gw >> 6;                              // 64 warps per batch element
    int t    = ((gw & 63) << 3) + (lane >> 2);
    int sub  = lane & 3;

    const float4* xp = (const float4*)(x + ((size_t)b * TT + t) * II);

    float acc[9];
#pragma unroll
    for (int g = 0; g < 9; g++) acc[g] = 0.f;

#pragma unroll
    for (int q = 0; q < 4; q++) {
        float4 xv = xp[sub + 4 * q];                 // interleaved strips
#pragma unroll
        for (int g = 0; g < 9; g++) {
            float4 wv = Ws4[g * 16 + sub + 4 * q];
            acc[g] = fmaf(xv.w, wv.w, fmaf(xv.z, wv.z,
                     fmaf(xv.y, wv.y, fmaf(xv.x, wv.x, acc[g]))));
        }
    }
#pragma unroll
    for (int g = 0; g < 9; g++) {
        acc[g] += __shfl_xor_sync(0xffffffffu, acc[g], 1);
        acc[g] += __shfl_xor_sync(0xffffffffu, acc[g], 2);
        acc[g] += bs[g];
    }
    if (sub < 3) {
        g_xw4[((size_t)t * 3 + sub) * BB + b] =
            make_float4(acc[sub], acc[3 + sub], acc[6 + sub], 0.f);
    }
}

// ---------------------------------------------------------------------------
// Phase B: 2 lanes per element. Even lane = layer 0; odd lane = layer 1,
// running one step behind and consuming h0 via 3 SHFLs. Loop body is fully
// branch-free; xw prefetched through a true 4-deep register ring.
// ---------------------------------------------------------------------------
__global__ void __launch_bounds__(32, 1) gru_rec(
    const float* __restrict__ W_hh0, const float* __restrict__ b_hh0,
    const float* __restrict__ W_ih1, const float* __restrict__ b_ih1,
    const float* __restrict__ W_hh1, const float* __restrict__ b_hh1,
    float* __restrict__ out)
{
    const int lane   = threadIdx.x;
    const int parity = lane & 1;                  // 0: layer0, 1: layer1
    const int e      = blockIdx.x * 16 + (lane >> 1);
    const int src    = lane & ~1;                 // partner (layer-0) lane

    // Own-layer recurrent weights; W_ih1 loaded by all lanes (used by odd only).
    const float* whh_p = parity ? W_hh1 : W_hh0;
    const float* bhh_p = parity ? b_hh1 : b_hh0;
    float wh[9][3], bh[9], wi[9][3], bi[9];
#pragma unroll
    for (int r = 0; r < 9; r++) {
        bh[r] = __ldg(bhh_p + r);
        bi[r] = __ldg(b_ih1 + r);
#pragma unroll
        for (int k = 0; k < 3; k++) {
            wh[r][k] = __ldg(whh_p + r * 3 + k);
            wi[r][k] = __ldg(W_ih1 + r * 3 + k);
        }
    }

    float h[3] = {0.f, 0.f, 0.f};

    const float4* xb = g_xw4 + e;
    float4 buf[4][3];
#pragma unroll
    for (int s = 0; s < 4; s++)
#pragma unroll
        for (int gf = 0; gf < 3; gf++)
            buf[s][gf] = xb[((size_t)s * 3 + gf) * BB];

    // One fused step: shfl h0, both matvecs, gates. hn returned, h not touched.
    auto step = [&](const float4 b4[3], float hn[3]) {
        float ho[3];
#pragma unroll
        for (int k = 0; k < 3; k++)
            ho[k] = __shfl_sync(0xffffffffu, h[k], src);
        float gh[9], ih[9];
#pragma unroll
        for (int r = 0; r < 9; r++) {
            gh[r] = fmaf(wh[r][2], h[2],  fmaf(wh[r][1], h[1],  fmaf(wh[r][0], h[0],  bh[r])));
            ih[r] = fmaf(wi[r][2], ho[2], fmaf(wi[r][1], ho[1], fmaf(wi[r][0], ho[0], bi[r])));
        }
#pragma unroll
        for (int j = 0; j < 3; j++) {
            float xr = parity ? ih[j]     : b4[j].x;
            float xz = parity ? ih[3 + j] : b4[j].y;
            float xn = parity ? ih[6 + j] : b4[j].z;
            float r  = sigm(xr + gh[j]);
            float z  = sigm(xz + gh[3 + j]);
            float n  = tanh_fast(fmaf(r, gh[6 + j], xn));
            hn[j] = fmaf(z, h[j] - n, n);
        }
    };

    // Peel t=0: layer-0 lanes commit h0^0; layer-1 lanes stay 0.
    {
        float hn[3];
        step(buf[0], hn);
#pragma unroll
        for (int j = 0; j < 3; j++) h[j] = parity ? 0.f : hn[j];
#pragma unroll
        for (int gf = 0; gf < 3; gf++)
            buf[0][gf] = xb[((size_t)4 * 3 + gf) * BB];
    }

    // Main loop t=1..511: even lanes compute h0^t, odd lanes h1^{t-1}.
#pragma unroll 4
    for (int t = 1; t < TT; t++) {
        float hn[3];
        step(buf[t & 3], hn);
#pragma unroll
        for (int j = 0; j < 3; j++) h[j] = hn[j];
#pragma unroll
        for (int gf = 0; gf < 3; gf++)
            buf[t & 3][gf] = xb[((size_t)(t + 4) * 3 + gf) * BB];  // pad region beyond T: zeros
    }

    // Epilogue: final layer-1 step consumes h0^{511}. Even-lane result discarded.
    {
        float hn[3];
        step(buf[0], hn);
#pragma unroll
        for (int j = 0; j < 3; j++) h[j] = parity ? hn[j] : h[j];
    }

    if (parity) {
        out[e * 3 + 0] = h[0];
        out[e * 3 + 1] = h[1];
        out[e * 3 + 2] = h[2];
    }
}

extern "C" void kernel_launch(void* const* d_in, const int* in_sizes, int n_in,
                              void* d_out, int out_size)
{
    const float* x     = (const float*)d_in[0];
    const float* W_ih0 = (const float*)d_in[1];
    const float* W_hh0 = (const float*)d_in[2];
    const float* b_ih0 = (const float*)d_in[3];
    const float* b_hh0 = (const float*)d_in[4];
    const float* W_ih1 = (const float*)d_in[5];
    const float* W_hh1 = (const float*)d_in[6];
    const float* b_ih1 = (const float*)d_in[7];
    const float* b_hh1 = (const float*)d_in[8];
    float* out = (float*)d_out;

    // 4 lanes per (b,t) cell -> B*T*4 threads
    phaseA<<<(BB * TT * 4) / 256, 256>>>(x, W_ih0, b_ih0);
    // 2 lanes per element -> B*2 threads, 1 warp per block for max SM spread
    gru_rec<<<BB * 2 / 32, 32>>>(W_hh0, b_hh0, W_ih1, b_ih1, W_hh1, b_hh1, out);
}